// round 6
// baseline (speedup 1.0000x reference)
#include <cuda_runtime.h>
#include <cuda_fp16.h>
#include <math.h>

typedef unsigned long long u64;

#define NIMG 16
#define NO   192
#define Hh   160
#define Wd   160
#define HW   25600
#define PAD  36

#define KHKW3 2916
#define P3    9
#define A3    26244
#define U3IMG 1679616
#define KHKW5 1024
#define P5    25
#define A5    25600
#define U5IMG 1638400
#define NPI   560

// ---------------- scratch ----------------
__device__ __align__(16) __half g_ex[(size_t)NIMG*NO*HW];
__device__ __align__(16) __half g_u3[(size_t)NIMG*U3IMG];
__device__ __align__(16) __half g_u5[(size_t)NIMG*U5IMG];
__device__ __align__(16) float g_sf3[NIMG*P3*KHKW3];
__device__ __align__(16) float g_sf5[NIMG*P5*KHKW5];
__device__ float g_Z[NPI], g_S[NPI*64], g_Pm[NPI*64];
__device__ float g_gt[NPI*64], g_veff[NPI*64], g_beff[NPI];
__device__ __align__(16) float g_W2t[NO*64];
__device__ __align__(16) float g_Ft[64*64];
__device__ float g_vb[64];
__device__ __align__(16) float g_expWt[64*NO];

// ---------------- helpers ----------------
__device__ __forceinline__ u64 pk2(float lo, float hi){
    u64 r; asm("mov.b64 %0,{%1,%2};":"=l"(r):"f"(lo),"f"(hi)); return r;
}
__device__ __forceinline__ void fma2(u64 &d, u64 a, u64 b){
    asm("fma.rn.f32x2 %0,%1,%2,%3;":"=l"(d):"l"(a),"l"(b),"l"(d));
}
__device__ __forceinline__ float2 up2(u64 v){
    float2 f; asm("mov.b64 {%0,%1},%2;":"=f"(f.x),"=f"(f.y):"l"(v)); return f;
}
__device__ __forceinline__ float sigf(float x){ return 1.f/(1.f+expf(-x)); }
__device__ __forceinline__ int cover3(int h, int* r){
    int n=0;
    #pragma unroll
    for(int i=0;i<3;i++){ int lo=53*i; if(h>=lo && h<=lo+53) r[n++]=i; }
    return n;
}

// ================ K0a: zero accumulators ================
__global__ void k_zero(){
    int i = blockIdx.x*256 + threadIdx.x;
    if(i < NPI) g_Z[i]=0.f;
    if(i < NPI*64){ g_S[i]=0.f; g_Pm[i]=0.f; }
}

// ================ K0b: weight prep ================
__global__ void k_wprep(const float* __restrict__ exp_w, const float* __restrict__ res_w,
                        const float* __restrict__ res_b, const float* __restrict__ fus_w,
                        const float* __restrict__ fus_b){
    int t = threadIdx.x;
    for(int i=t;i<64*NO;i+=256){ int c=i/NO, o=i%NO; g_expWt[i]=exp_w[o*64+c]; }
    for(int i=t;i<64*64;i+=256){ int c=i/64, o=i%64; g_Ft[i]=fus_w[o*64+c]; }
    for(int i=t;i<NO*64;i+=256){
        int k=i/64, o=i%64; float s=0.f;
        for(int c=0;c<64;c++) s += fus_w[o*64+c]*res_w[c*NO+k];
        g_W2t[i]=s;
    }
    for(int o=t;o<64;o+=256){
        float s=fus_b[o];
        for(int c=0;c<64;c++) s += fus_w[o*64+c]*res_b[c];
        g_vb[o]=s;
    }
}

// ================ K1: ex = Wexp @ x + fused win1 stats ================
__global__ void __launch_bounds__(256) k1(const float* __restrict__ x,
                                          const float* __restrict__ exp_b,
                                          const float* __restrict__ wq,
                                          const float* __restrict__ wqb){
    __shared__ __align__(16) float xs[64*PAD];
    __shared__ float exs0[64*33];
    __shared__ float es[32];
    int t = threadIdx.x;
    int wt = blockIdx.x, h = blockIdx.y, n = blockIdx.z;
    int w0 = wt*32;

    const float* xp = x + (size_t)n*64*HW + (size_t)h*Wd + w0;
    for(int i=t;i<512;i+=256){
        int c=i>>3, grp=(i&7)*4;
        *(float4*)&xs[c*PAD+grp] = *(const float4*)&xp[(size_t)c*HW+grp];
    }
    __syncthreads();

    int ob = t&63, pg = t>>6, pb = pg*8;
    u64 acc[3][4];
    #pragma unroll
    for(int a=0;a<3;a++)
        #pragma unroll
        for(int j=0;j<4;j++) acc[a][j]=0ull;
    for(int c=0;c<64;c++){
        u64 xv[4];
        #pragma unroll
        for(int j=0;j<4;j++) xv[j]=*(const u64*)&xs[c*PAD+pb+j*2];
        #pragma unroll
        for(int a=0;a<3;a++){
            float w = g_expWt[c*NO + ob + a*64];
            u64 wp = pk2(w,w);
            #pragma unroll
            for(int j=0;j<4;j++) fma2(acc[a][j], wp, xv[j]);
        }
    }
    __half* exg = g_ex + (size_t)n*NO*HW + (size_t)h*Wd + w0;
    #pragma unroll
    for(int a=0;a<3;a++){
        float b = exp_b[ob+a*64];
        float2 v0=up2(acc[a][0]), v1=up2(acc[a][1]), v2=up2(acc[a][2]), v3=up2(acc[a][3]);
        if(a==0){
            float* d = &exs0[ob*33 + pb];
            d[0]=v0.x+b; d[1]=v0.y+b; d[2]=v1.x+b; d[3]=v1.y+b;
            d[4]=v2.x+b; d[5]=v2.y+b; d[6]=v3.x+b; d[7]=v3.y+b;
        }
        __half2 h0=__floats2half2_rn(v0.x+b, v0.y+b);
        __half2 h1=__floats2half2_rn(v1.x+b, v1.y+b);
        __half2 h2=__floats2half2_rn(v2.x+b, v2.y+b);
        __half2 h3=__floats2half2_rn(v3.x+b, v3.y+b);
        uint4 pk;
        pk.x=*(unsigned*)&h0; pk.y=*(unsigned*)&h1;
        pk.z=*(unsigned*)&h2; pk.w=*(unsigned*)&h3;
        *(uint4*)&exg[(size_t)(ob+a*64)*HW + pb] = pk;
    }
    __syncthreads();

    // fused win1 stats: qdot + e per pixel
    if(t<32){
        float qd = wqb[0];
        #pragma unroll
        for(int c=0;c<64;c++) qd += wq[c]*exs0[c*33+t];
        float e = expf(qd);
        es[t]=e;
        float z=e;
        for(int off=16;off;off>>=1) z += __shfl_xor_sync(0xffffffffu,z,off);
        if(t==0) atomicAdd(&g_Z[n], z);
    }
    __syncthreads();
    if(t<64){
        float Ps=0.f, Ss=0.f;
        #pragma unroll
        for(int px=0;px<32;px++){ float v=exs0[t*33+px]; Ps+=v; Ss+=v*es[px]; }
        atomicAdd(&g_S[n*64+t], Ss);
        atomicAdd(&g_Pm[n*64+t], Ps);
    }
}

// ================ K2: repack into unfold order (warp-per-ci, fp16) ================
__global__ void __launch_bounds__(256) k2_5(){
    __shared__ __align__(16) __half rb[8][800];
    int y = blockIdx.x, n = blockIdx.y;
    int wp = threadIdx.x >> 5, lane = threadIdx.x & 31;
    for(int cit=0; cit<8; cit++){
        int ci = cit*8 + wp;
        const __half* src = g_ex + (size_t)n*NO*HW + (size_t)(128+ci)*HW;
        #pragma unroll
        for(int ph=0; ph<5; ph++){
            const __half2* row2 = (const __half2*)(src + (size_t)(ph*32+y)*Wd);
            #pragma unroll
            for(int it=0; it<3; it++){
                int idx = lane + it*32;
                if(idx<80){
                    __half2 v = row2[idx];
                    int w = idx*2, pw = w>>5, xx = w&31;
                    rb[wp][xx*25 + ph*5 + pw]     = __low2half(v);
                    rb[wp][(xx+1)*25 + ph*5 + pw] = __high2half(v);
                }
            }
        }
        __syncwarp();
        uint4* dst = (uint4*)(g_u5 + (size_t)n*U5IMG + (size_t)(ci*1024 + y*32)*25);
        const uint4* s = (const uint4*)rb[wp];
        #pragma unroll
        for(int it=0; it<4; it++){
            int k = lane + it*32;
            if(k < 100) dst[k] = s[k];
        }
        __syncwarp();
    }
}
__global__ void __launch_bounds__(256) k2_3(){
    __shared__ __align__(16) __half rb[8][488];
    int yy = blockIdx.x, n = blockIdx.y;
    int wp = threadIdx.x >> 5, lane = threadIdx.x & 31;
    for(int cit=0; cit<8; cit++){
        int ci = cit*8 + wp;
        const __half* src = g_ex + (size_t)n*NO*HW + (size_t)(64+ci)*HW;
        #pragma unroll
        for(int ph=0; ph<3; ph++){
            const __half2* row2 = (const __half2*)(src + (size_t)(53*ph+yy)*Wd);
            #pragma unroll
            for(int it=0; it<3; it++){
                int idx = lane + it*32;
                if(idx<80){
                    __half2 v = row2[idx];
                    int w0_ = idx*2;
                    __half hv[2] = {__low2half(v), __high2half(v)};
                    #pragma unroll
                    for(int hh=0; hh<2; hh++){
                        int w = w0_ + hh;
                        #pragma unroll
                        for(int pw=0; pw<3; pw++){
                            int xx = w - 53*pw;
                            if(xx>=0 && xx<54) rb[wp][xx*9 + ph*3 + pw] = hv[hh];
                        }
                    }
                }
            }
        }
        __syncwarp();
        unsigned* dst = (unsigned*)(g_u3 + (size_t)n*U3IMG + (size_t)ci*A3 + (size_t)yy*486);
        const unsigned* s = (const unsigned*)rb[wp];
        #pragma unroll
        for(int it=0; it<8; it++){
            int k = lane + it*32;
            if(k < 243) dst[k] = s[k];
        }
        __syncwarp();
    }
}

// ================ K3: stats (fp16 smem, q-tile 128) ================
__global__ void __launch_bounds__(256) k_stats(const __half* __restrict__ ub, int khkw,
                                               size_t imgstride, int piBase,
                                               const float* __restrict__ wq,
                                               const float* __restrict__ wqb){
    __shared__ __half Vs[64*130];
    __shared__ float part[4*128];
    __shared__ float es[128];
    int q0 = blockIdx.x*128, bp = blockIdx.y, n = blockIdx.z;
    int t = threadIdx.x;
    const __half* base = ub + (size_t)n*imgstride + (size_t)bp*64*khkw + q0;
    int qlim = khkw - q0; if(qlim>128) qlim=128;

    for(int i=t;i<4096;i+=256){
        int c=i>>6, j2=i&63;
        unsigned v = 0;
        if(j2*2 < qlim) v = *(const unsigned*)&base[(size_t)c*khkw + j2*2];
        *(unsigned*)&Vs[c*130 + j2*2] = v;
    }
    __syncthreads();
    {
        int j2=t&63, cg=t>>6;
        float sx=0.f, sy=0.f;
        #pragma unroll 8
        for(int cc=cg*16; cc<cg*16+16; cc++){
            float2 f = __half22float2(*(const __half2*)&Vs[cc*130 + j2*2]);
            float w = wq[cc];
            sx += w*f.x; sy += w*f.y;
        }
        part[cg*128 + j2*2]   = sx;
        part[cg*128 + j2*2+1] = sy;
    }
    __syncthreads();
    int pi = piBase + n*gridDim.y + bp;
    if(t<128){
        float qd = part[t]+part[128+t]+part[256+t]+part[384+t] + wqb[0];
        float e = (t<qlim) ? expf(qd) : 0.f;
        es[t]=e;
        float z=e;
        for(int off=16;off;off>>=1) z += __shfl_xor_sync(0xffffffffu,z,off);
        if((t&31)==0) atomicAdd(&g_Z[pi], z);
    }
    __syncthreads();
    {
        int c=t&63, jg=t>>6;
        float ss=0.f, pm=0.f;
        #pragma unroll 8
        for(int j2=jg*16; j2<jg*16+16; j2++){
            float2 f = __half22float2(*(const __half2*)&Vs[c*130 + j2*2]);
            ss += f.x*es[2*j2] + f.y*es[2*j2+1];
            pm += f.x + f.y;
        }
        atomicAdd(&g_S[pi*64+c], ss);
        atomicAdd(&g_Pm[pi*64+c], pm);
    }
}

// ================ K4: per-pseudo-image finalize ================
__global__ void __launch_bounds__(64) k4(const float* __restrict__ chwv_w, const float* __restrict__ chwv_b,
                                         const float* __restrict__ chwz_w, const float* __restrict__ chwz_b,
                                         const float* __restrict__ ln_g,  const float* __restrict__ ln_b,
                                         const float* __restrict__ spwq_w,const float* __restrict__ spwq_b,
                                         const float* __restrict__ spwv_w,const float* __restrict__ spwv_b){
    int p = blockIdx.x, t = threadIdx.x;
    float hw = (p<16) ? 25600.f : ((p<160) ? 2916.f : 1024.f);
    __shared__ float xbar[64], pmean[64], wz[32], red[64], swq[32];

    float Zinv = 1.f/g_Z[p];
    xbar[t]  = g_S[p*64+t]*Zinv;
    pmean[t] = g_Pm[p*64+t]/hw;
    __syncthreads();

    if(t<32){
        float s = chwv_b[t];
        for(int c=0;c<64;c++) s += chwv_w[t*64+c]*xbar[c];
        wz[t]=s;
    }
    __syncthreads();

    float z = chwz_b[t];
    for(int j=0;j<32;j++) z += chwz_w[t*32+j]*wz[j];

    red[t]=z; __syncthreads();
    for(int s=32;s>0;s>>=1){ if(t<s) red[t]+=red[t+s]; __syncthreads(); }
    float mu = red[0]*(1.f/64.f); __syncthreads();
    float d = z-mu;
    red[t]=d*d; __syncthreads();
    for(int s=32;s>0;s>>=1){ if(t<s) red[t]+=red[t+s]; __syncthreads(); }
    float var = red[0]*(1.f/64.f);

    float zn = d*rsqrtf(var+1e-5f)*ln_g[t] + ln_b[t];
    g_gt[p*64+t] = sigf(zn);
    __syncthreads();

    if(t<32){
        float s = spwq_b[t];
        for(int c=0;c<64;c++) s += spwq_w[t*64+c]*pmean[c];
        float m=s;
        for(int off=16;off;off>>=1) m=fmaxf(m,__shfl_xor_sync(0xffffffffu,m,off));
        float e=expf(s-m), sum=e;
        for(int off=16;off;off>>=1) sum+=__shfl_xor_sync(0xffffffffu,sum,off);
        swq[t]=e/sum;
    }
    __syncthreads();

    float v=0.f;
    for(int j=0;j<32;j++) v += swq[j]*spwv_w[j*64+t];
    g_veff[p*64+t]=v;
    if(t==0){
        float b=0.f;
        for(int j=0;j<32;j++) b += swq[j]*spwv_b[j];
        g_beff[p]=b;
    }
}

// ================ K5: s-field (fp16 smem, q-tile 128) ================
__global__ void __launch_bounds__(256) k_sfield(const __half* __restrict__ ub, int khkw,
                                                size_t imgstride, int piBase,
                                                float* __restrict__ sf){
    __shared__ __half Vs[64*130];
    __shared__ float part[4*128];
    __shared__ float ve[64];
    int q0 = blockIdx.x*128, bp = blockIdx.y, n = blockIdx.z;
    int t = threadIdx.x;
    int pi = piBase + n*gridDim.y + bp;
    const __half* base = ub + (size_t)n*imgstride + (size_t)bp*64*khkw + q0;
    int qlim = khkw - q0; if(qlim>128) qlim=128;

    if(t<64) ve[t]=g_veff[pi*64+t];
    for(int i=t;i<4096;i+=256){
        int c=i>>6, j2=i&63;
        unsigned v = 0;
        if(j2*2 < qlim) v = *(const unsigned*)&base[(size_t)c*khkw + j2*2];
        *(unsigned*)&Vs[c*130 + j2*2] = v;
    }
    __syncthreads();
    {
        int j2=t&63, cg=t>>6;
        float sx=0.f, sy=0.f;
        #pragma unroll 8
        for(int cc=cg*16; cc<cg*16+16; cc++){
            float2 f = __half22float2(*(const __half2*)&Vs[cc*130 + j2*2]);
            float w = ve[cc];
            sx += w*f.x; sy += w*f.y;
        }
        part[cg*128 + j2*2]   = sx;
        part[cg*128 + j2*2+1] = sy;
    }
    __syncthreads();
    if(t<128 && t<qlim){
        float sd = part[t]+part[128+t]+part[256+t]+part[384+t] + g_beff[pi];
        sf[(size_t)n*(gridDim.y*khkw) + (size_t)bp*khkw + q0 + t] = sigf(sd);
    }
}

// ================ K6: in-block s1 + div-free multiplier + fused GEMM ================
__global__ void __launch_bounds__(256) k6(const float* __restrict__ x, float* __restrict__ out){
    __shared__ __align__(16) float exs[NO*PAD];
    __shared__ __align__(16) float xs[64*PAD];
    __shared__ float s1s[32], icntS[32];
    __shared__ int q5s[32], cp05s[32];
    __shared__ int q3s[4][32], cp03s[4][32];
    __shared__ int nsegS[32];
    __shared__ int nrS;

    int t = threadIdx.x;
    int wt = blockIdx.x, h = blockIdx.y, n = blockIdx.z;
    int w0 = wt*32;

    const __half* exg = g_ex + (size_t)n*NO*HW + (size_t)h*Wd + w0;
    for(int i=t;i<768;i+=256){
        int k=i>>2, q=(i&3)*8;
        uint4 raw = *(const uint4*)&exg[(size_t)k*HW + q];
        __half2* hp = (__half2*)&raw;
        float2 f0=__half22float2(hp[0]), f1=__half22float2(hp[1]);
        float2 f2=__half22float2(hp[2]), f3=__half22float2(hp[3]);
        float* d = &exs[k*PAD+q];
        d[0]=f0.x; d[1]=f0.y; d[2]=f1.x; d[3]=f1.y;
        d[4]=f2.x; d[5]=f2.y; d[6]=f3.x; d[7]=f3.y;
    }
    const float* xp = x + (size_t)n*64*HW + (size_t)h*Wd + w0;
    for(int i=t;i<512;i+=256){
        int c=i>>3, grp=(i&7)*4;
        *(float4*)&xs[c*PAD+grp] = *(const float4*)&xp[(size_t)c*HW+grp];
    }
    if(t<32){
        int w = w0 + t;
        // win5 precompute
        int rp5 = ((h&31)*32 + (w&31))*P5 + (h>>5)*5 + (w>>5);
        q5s[t] = rp5 & 1023; cp05s[t] = rp5 >> 10;
        // win3 precompute
        int R[2], C[2];
        int nr = cover3(h, R), nc = cover3(w, C);
        if(t==0) nrS = nr;
        nsegS[t] = nr*nc;
        icntS[t] = 1.f/(float)(nr*nc);
        for(int ri=0;ri<nr;ri++)
            for(int cj=0;cj<nc;cj++){
                int ph=R[ri], pw=C[cj];
                int rp3 = ((h-53*ph)*54 + (w-53*pw))*P3 + ph*3 + pw;
                int s = ri*nc + cj;
                cp03s[s][t] = rp3 / KHKW3;
                q3s[s][t]   = rp3 % KHKW3;
            }
    }
    __syncthreads();

    // in-block win1 s-field from raw chunk0
    if(t<32){
        float sd = g_beff[n];
        const float* ve = &g_veff[n*64];
        #pragma unroll
        for(int c=0;c<64;c++) sd += ve[c]*exs[c*PAD+t];
        s1s[t] = sigf(sd);
    }
    __syncthreads();

    // multiplier (div-free)
    for(int i=t;i<NO*32;i+=256){
        int k=i>>5, pix=i&31, win=k>>6, ci=k&63;
        float m;
        if(win==0){
            m = g_gt[n*64+ci] + s1s[pix];
        } else if(win==2){
            int cpv = cp05s[pix] + 25*ci;
            int bp = cpv>>6, cp = cpv&63;
            m = g_gt[(160+n*25+bp)*64+cp] + g_sf5[n*25600 + (bp<<10) + q5s[pix]];
        } else {
            m = 0.f;
            int ns = nsegS[pix];
            #pragma unroll
            for(int s=0;s<4;s++){
                if(s>=ns) break;
                int cpv = cp03s[s][pix] + 9*ci;
                int bp = cpv>>6, cp = cpv&63;
                m += g_gt[(16+n*9+bp)*64+cp] + g_sf3[n*A3 + bp*KHKW3 + q3s[s][pix]];
            }
            m *= icntS[pix];
        }
        exs[k*PAD+pix] *= (1.f + m);
    }
    __syncthreads();

    int ob = t&63, pg = t>>6, pb = pg*8;
    float vbv = g_vb[ob];
    u64 acc[4];
    #pragma unroll
    for(int j=0;j<4;j++) acc[j]=pk2(vbv,vbv);
    for(int k=0;k<NO;k++){
        float wv = g_W2t[k*64+ob];
        u64 wp = pk2(wv,wv);
        #pragma unroll
        for(int j=0;j<4;j++){ u64 ev=*(const u64*)&exs[k*PAD+pb+j*2]; fma2(acc[j],wp,ev); }
    }
    for(int c=0;c<64;c++){
        float fv = g_Ft[c*64+ob];
        u64 fp = pk2(fv,fv);
        #pragma unroll
        for(int j=0;j<4;j++){ u64 xv=*(const u64*)&xs[c*PAD+pb+j*2]; fma2(acc[j],fp,xv); }
    }
    __syncthreads();
    #pragma unroll
    for(int j=0;j<4;j++){
        float2 v=up2(acc[j]);
        xs[ob*PAD+pb+j*2  ]=v.x;
        xs[ob*PAD+pb+j*2+1]=v.y;
    }
    __syncthreads();
    float* og = out + (size_t)n*64*HW + (size_t)h*Wd + w0;
    for(int i=t;i<512;i+=256){
        int o=i>>3, grp=(i&7)*4;
        *(float4*)&og[(size_t)o*HW+grp] = *(const float4*)&xs[o*PAD+grp];
    }
}

// ================ launch ================
extern "C" void kernel_launch(void* const* d_in, const int* in_sizes, int n_in,
                              void* d_out, int out_size){
    const float* x      = (const float*)d_in[0];
    const float* exp_w  = (const float*)d_in[1];
    const float* exp_b  = (const float*)d_in[2];
    const float* res_w  = (const float*)d_in[3];
    const float* res_b  = (const float*)d_in[4];
    const float* fus_w  = (const float*)d_in[5];
    const float* fus_b  = (const float*)d_in[6];
    const float* chwv_w = (const float*)d_in[7];
    const float* chwv_b = (const float*)d_in[8];
    const float* chwq_w = (const float*)d_in[9];
    const float* chwq_b = (const float*)d_in[10];
    const float* chwz_w = (const float*)d_in[11];
    const float* chwz_b = (const float*)d_in[12];
    const float* ln_g   = (const float*)d_in[13];
    const float* ln_b   = (const float*)d_in[14];
    const float* spwv_w = (const float*)d_in[15];
    const float* spwv_b = (const float*)d_in[16];
    const float* spwq_w = (const float*)d_in[17];
    const float* spwq_b = (const float*)d_in[18];
    float* out = (float*)d_out;

    __half *g_u3_p, *g_u5_p;
    float *g_sf3_p, *g_sf5_p;
    cudaGetSymbolAddress((void**)&g_u3_p, g_u3);
    cudaGetSymbolAddress((void**)&g_u5_p, g_u5);
    cudaGetSymbolAddress((void**)&g_sf3_p, g_sf3);
    cudaGetSymbolAddress((void**)&g_sf5_p, g_sf5);

    k_zero<<<(NPI*64+255)/256, 256>>>();
    k_wprep<<<1, 256>>>(exp_w, res_w, res_b, fus_w, fus_b);

    dim3 grid(Wd/32, Hh, NIMG);
    k1<<<grid, 256>>>(x, exp_b, chwq_w, chwq_b);

    k2_5<<<dim3(32,NIMG), 256>>>();
    k2_3<<<dim3(54,NIMG), 256>>>();

    k_stats<<<dim3(23,  9, NIMG), 256>>>(g_u3_p, KHKW3,(size_t)U3IMG, 16,  chwq_w, chwq_b);
    k_stats<<<dim3(8,  25, NIMG), 256>>>(g_u5_p, KHKW5,(size_t)U5IMG, 160, chwq_w, chwq_b);

    k4<<<NPI, 64>>>(chwv_w, chwv_b, chwz_w, chwz_b, ln_g, ln_b,
                    spwq_w, spwq_b, spwv_w, spwv_b);

    k_sfield<<<dim3(23,  9, NIMG), 256>>>(g_u3_p, KHKW3,(size_t)U3IMG, 16,  g_sf3_p);
    k_sfield<<<dim3(8,  25, NIMG), 256>>>(g_u5_p, KHKW5,(size_t)U5IMG, 160, g_sf5_p);

    k6<<<grid, 256>>>(x, out);
}

// round 7
// speedup vs baseline: 1.3632x; 1.3632x over previous
#include <cuda_runtime.h>
#include <cuda_fp16.h>
#include <math.h>

typedef unsigned long long u64;

#define NIMG 16
#define NO   192
#define Hh   160
#define Wd   160
#define HW   25600
#define PAD  36

#define KHKW3 2916
#define P3    9
#define A3    26244
#define U3IMG 1679616
#define KHKW5 1024
#define P5    25
#define A5    25600
#define U5IMG 1638400
#define NPI   560

// ---------------- scratch ----------------
__device__ __align__(16) __half g_ex[(size_t)NIMG*NO*HW];
__device__ __align__(16) __half g_u3[(size_t)NIMG*U3IMG];
__device__ __align__(16) __half g_u5[(size_t)NIMG*U5IMG];
__device__ __align__(16) float g_sf3[NIMG*P3*KHKW3];
__device__ __align__(16) float g_sf5[NIMG*P5*KHKW5];
__device__ float g_Z[NPI], g_S[NPI*64], g_Pm[NPI*64];
__device__ float g_gt[NPI*64], g_veff[NPI*64], g_beff[NPI];
__device__ __align__(16) float g_Wall[256*64];   // rows 0..191: fus@res [k][o]; 192..255: fus^T [c][o]
__device__ float g_vb[64];
__device__ __align__(16) float g_expWt[64*NO];

// ---------------- helpers ----------------
__device__ __forceinline__ u64 pk2(float lo, float hi){
    u64 r; asm("mov.b64 %0,{%1,%2};":"=l"(r):"f"(lo),"f"(hi)); return r;
}
__device__ __forceinline__ void fma2(u64 &d, u64 a, u64 b){
    asm("fma.rn.f32x2 %0,%1,%2,%3;":"=l"(d):"l"(a),"l"(b),"l"(d));
}
__device__ __forceinline__ float2 up2(u64 v){
    float2 f; asm("mov.b64 {%0,%1},%2;":"=f"(f.x),"=f"(f.y):"l"(v)); return f;
}
__device__ __forceinline__ float sigf(float x){ return 1.f/(1.f+expf(-x)); }
__device__ __forceinline__ int cover3(int h, int* r){
    int n=0;
    #pragma unroll
    for(int i=0;i<3;i++){ int lo=53*i; if(h>=lo && h<=lo+53) r[n++]=i; }
    return n;
}

// ================ K0a: zero accumulators ================
__global__ void k_zero(){
    int i = blockIdx.x*256 + threadIdx.x;
    if(i < NPI) g_Z[i]=0.f;
    if(i < NPI*64){ g_S[i]=0.f; g_Pm[i]=0.f; }
}

// ================ K0b: weight prep ================
__global__ void k_wprep(const float* __restrict__ exp_w, const float* __restrict__ res_w,
                        const float* __restrict__ res_b, const float* __restrict__ fus_w,
                        const float* __restrict__ fus_b){
    int t = threadIdx.x;
    for(int i=t;i<64*NO;i+=256){ int c=i/NO, o=i%NO; g_expWt[i]=exp_w[o*64+c]; }
    for(int i=t;i<NO*64;i+=256){
        int k=i/64, o=i%64; float s=0.f;
        for(int c=0;c<64;c++) s += fus_w[o*64+c]*res_w[c*NO+k];
        g_Wall[i]=s;
    }
    for(int i=t;i<64*64;i+=256){ int c=i/64, o=i%64; g_Wall[(192+c)*64+o]=fus_w[o*64+c]; }
    for(int o=t;o<64;o+=256){
        float s=fus_b[o];
        for(int c=0;c<64;c++) s += fus_w[o*64+c]*res_b[c];
        g_vb[o]=s;
    }
}

// ================ K1: ex = Wexp @ x + fused win1 stats ================
__global__ void __launch_bounds__(256) k1(const float* __restrict__ x,
                                          const float* __restrict__ exp_b,
                                          const float* __restrict__ wq,
                                          const float* __restrict__ wqb){
    __shared__ __align__(16) float xs[64*PAD];
    __shared__ float exs0[64*33];
    __shared__ float es[32];
    int t = threadIdx.x;
    int wt = blockIdx.x, h = blockIdx.y, n = blockIdx.z;
    int w0 = wt*32;

    const float* xp = x + (size_t)n*64*HW + (size_t)h*Wd + w0;
    for(int i=t;i<512;i+=256){
        int c=i>>3, grp=(i&7)*4;
        *(float4*)&xs[c*PAD+grp] = *(const float4*)&xp[(size_t)c*HW+grp];
    }
    __syncthreads();

    int ob = t&63, pg = t>>6, pb = pg*8;
    u64 acc[3][4];
    #pragma unroll
    for(int a=0;a<3;a++)
        #pragma unroll
        for(int j=0;j<4;j++) acc[a][j]=0ull;
    for(int c=0;c<64;c++){
        u64 xv[4];
        #pragma unroll
        for(int j=0;j<4;j++) xv[j]=*(const u64*)&xs[c*PAD+pb+j*2];
        #pragma unroll
        for(int a=0;a<3;a++){
            float w = g_expWt[c*NO + ob + a*64];
            u64 wp = pk2(w,w);
            #pragma unroll
            for(int j=0;j<4;j++) fma2(acc[a][j], wp, xv[j]);
        }
    }
    __half* exg = g_ex + (size_t)n*NO*HW + (size_t)h*Wd + w0;
    #pragma unroll
    for(int a=0;a<3;a++){
        float b = exp_b[ob+a*64];
        float2 v0=up2(acc[a][0]), v1=up2(acc[a][1]), v2=up2(acc[a][2]), v3=up2(acc[a][3]);
        if(a==0){
            float* d = &exs0[ob*33 + pb];
            d[0]=v0.x+b; d[1]=v0.y+b; d[2]=v1.x+b; d[3]=v1.y+b;
            d[4]=v2.x+b; d[5]=v2.y+b; d[6]=v3.x+b; d[7]=v3.y+b;
        }
        __half2 h0=__floats2half2_rn(v0.x+b, v0.y+b);
        __half2 h1=__floats2half2_rn(v1.x+b, v1.y+b);
        __half2 h2=__floats2half2_rn(v2.x+b, v2.y+b);
        __half2 h3=__floats2half2_rn(v3.x+b, v3.y+b);
        uint4 pk;
        pk.x=*(unsigned*)&h0; pk.y=*(unsigned*)&h1;
        pk.z=*(unsigned*)&h2; pk.w=*(unsigned*)&h3;
        *(uint4*)&exg[(size_t)(ob+a*64)*HW + pb] = pk;
    }
    __syncthreads();

    if(t<32){
        float qd = wqb[0];
        #pragma unroll
        for(int c=0;c<64;c++) qd += wq[c]*exs0[c*33+t];
        float e = expf(qd);
        es[t]=e;
        float z=e;
        for(int off=16;off;off>>=1) z += __shfl_xor_sync(0xffffffffu,z,off);
        if(t==0) atomicAdd(&g_Z[n], z);
    }
    __syncthreads();
    if(t<64){
        float Ps=0.f, Ss=0.f;
        #pragma unroll
        for(int px=0;px<32;px++){ float v=exs0[t*33+px]; Ps+=v; Ss+=v*es[px]; }
        atomicAdd(&g_S[n*64+t], Ss);
        atomicAdd(&g_Pm[n*64+t], Ps);
    }
}

// ================ K2: repack into unfold order (warp-per-ci, fp16) ================
__global__ void __launch_bounds__(256) k2_5(){
    __shared__ __align__(16) __half rb[8][800];
    int y = blockIdx.x, n = blockIdx.y;
    int wp = threadIdx.x >> 5, lane = threadIdx.x & 31;
    for(int cit=0; cit<8; cit++){
        int ci = cit*8 + wp;
        const __half* src = g_ex + (size_t)n*NO*HW + (size_t)(128+ci)*HW;
        #pragma unroll
        for(int ph=0; ph<5; ph++){
            const __half2* row2 = (const __half2*)(src + (size_t)(ph*32+y)*Wd);
            #pragma unroll
            for(int it=0; it<3; it++){
                int idx = lane + it*32;
                if(idx<80){
                    __half2 v = row2[idx];
                    int w = idx*2, pw = w>>5, xx = w&31;
                    rb[wp][xx*25 + ph*5 + pw]     = __low2half(v);
                    rb[wp][(xx+1)*25 + ph*5 + pw] = __high2half(v);
                }
            }
        }
        __syncwarp();
        uint4* dst = (uint4*)(g_u5 + (size_t)n*U5IMG + (size_t)(ci*1024 + y*32)*25);
        const uint4* s = (const uint4*)rb[wp];
        #pragma unroll
        for(int it=0; it<4; it++){
            int k = lane + it*32;
            if(k < 100) dst[k] = s[k];
        }
        __syncwarp();
    }
}
__global__ void __launch_bounds__(256) k2_3(){
    __shared__ __align__(16) __half rb[8][488];
    int yy = blockIdx.x, n = blockIdx.y;
    int wp = threadIdx.x >> 5, lane = threadIdx.x & 31;
    for(int cit=0; cit<8; cit++){
        int ci = cit*8 + wp;
        const __half* src = g_ex + (size_t)n*NO*HW + (size_t)(64+ci)*HW;
        #pragma unroll
        for(int ph=0; ph<3; ph++){
            const __half2* row2 = (const __half2*)(src + (size_t)(53*ph+yy)*Wd);
            #pragma unroll
            for(int it=0; it<3; it++){
                int idx = lane + it*32;
                if(idx<80){
                    __half2 v = row2[idx];
                    int w0_ = idx*2;
                    __half hv[2] = {__low2half(v), __high2half(v)};
                    #pragma unroll
                    for(int hh=0; hh<2; hh++){
                        int w = w0_ + hh;
                        #pragma unroll
                        for(int pw=0; pw<3; pw++){
                            int xx = w - 53*pw;
                            if(xx>=0 && xx<54) rb[wp][xx*9 + ph*3 + pw] = hv[hh];
                        }
                    }
                }
            }
        }
        __syncwarp();
        unsigned* dst = (unsigned*)(g_u3 + (size_t)n*U3IMG + (size_t)ci*A3 + (size_t)yy*486);
        const unsigned* s = (const unsigned*)rb[wp];
        #pragma unroll
        for(int it=0; it<8; it++){
            int k = lane + it*32;
            if(k < 243) dst[k] = s[k];
        }
        __syncwarp();
    }
}

// ================ K3: stats (fp16 smem, q-tile 128) ================
__global__ void __launch_bounds__(256) k_stats(const __half* __restrict__ ub, int khkw,
                                               size_t imgstride, int piBase,
                                               const float* __restrict__ wq,
                                               const float* __restrict__ wqb){
    __shared__ __half Vs[64*130];
    __shared__ float part[4*128];
    __shared__ float es[128];
    int q0 = blockIdx.x*128, bp = blockIdx.y, n = blockIdx.z;
    int t = threadIdx.x;
    const __half* base = ub + (size_t)n*imgstride + (size_t)bp*64*khkw + q0;
    int qlim = khkw - q0; if(qlim>128) qlim=128;

    for(int i=t;i<4096;i+=256){
        int c=i>>6, j2=i&63;
        unsigned v = 0;
        if(j2*2 < qlim) v = *(const unsigned*)&base[(size_t)c*khkw + j2*2];
        *(unsigned*)&Vs[c*130 + j2*2] = v;
    }
    __syncthreads();
    {
        int j2=t&63, cg=t>>6;
        float sx=0.f, sy=0.f;
        #pragma unroll 8
        for(int cc=cg*16; cc<cg*16+16; cc++){
            float2 f = __half22float2(*(const __half2*)&Vs[cc*130 + j2*2]);
            float w = wq[cc];
            sx += w*f.x; sy += w*f.y;
        }
        part[cg*128 + j2*2]   = sx;
        part[cg*128 + j2*2+1] = sy;
    }
    __syncthreads();
    int pi = piBase + n*gridDim.y + bp;
    if(t<128){
        float qd = part[t]+part[128+t]+part[256+t]+part[384+t] + wqb[0];
        float e = (t<qlim) ? expf(qd) : 0.f;
        es[t]=e;
        float z=e;
        for(int off=16;off;off>>=1) z += __shfl_xor_sync(0xffffffffu,z,off);
        if((t&31)==0) atomicAdd(&g_Z[pi], z);
    }
    __syncthreads();
    {
        int c=t&63, jg=t>>6;
        float ss=0.f, pm=0.f;
        #pragma unroll 8
        for(int j2=jg*16; j2<jg*16+16; j2++){
            float2 f = __half22float2(*(const __half2*)&Vs[c*130 + j2*2]);
            ss += f.x*es[2*j2] + f.y*es[2*j2+1];
            pm += f.x + f.y;
        }
        atomicAdd(&g_S[pi*64+c], ss);
        atomicAdd(&g_Pm[pi*64+c], pm);
    }
}

// ================ K4: per-pseudo-image finalize ================
__global__ void __launch_bounds__(64) k4(const float* __restrict__ chwv_w, const float* __restrict__ chwv_b,
                                         const float* __restrict__ chwz_w, const float* __restrict__ chwz_b,
                                         const float* __restrict__ ln_g,  const float* __restrict__ ln_b,
                                         const float* __restrict__ spwq_w,const float* __restrict__ spwq_b,
                                         const float* __restrict__ spwv_w,const float* __restrict__ spwv_b){
    int p = blockIdx.x, t = threadIdx.x;
    float hw = (p<16) ? 25600.f : ((p<160) ? 2916.f : 1024.f);
    __shared__ float xbar[64], pmean[64], wz[32], red[64], swq[32];

    float Zinv = 1.f/g_Z[p];
    xbar[t]  = g_S[p*64+t]*Zinv;
    pmean[t] = g_Pm[p*64+t]/hw;
    __syncthreads();

    if(t<32){
        float s = chwv_b[t];
        for(int c=0;c<64;c++) s += chwv_w[t*64+c]*xbar[c];
        wz[t]=s;
    }
    __syncthreads();

    float z = chwz_b[t];
    for(int j=0;j<32;j++) z += chwz_w[t*32+j]*wz[j];

    red[t]=z; __syncthreads();
    for(int s=32;s>0;s>>=1){ if(t<s) red[t]+=red[t+s]; __syncthreads(); }
    float mu = red[0]*(1.f/64.f); __syncthreads();
    float d = z-mu;
    red[t]=d*d; __syncthreads();
    for(int s=32;s>0;s>>=1){ if(t<s) red[t]+=red[t+s]; __syncthreads(); }
    float var = red[0]*(1.f/64.f);

    float zn = d*rsqrtf(var+1e-5f)*ln_g[t] + ln_b[t];
    g_gt[p*64+t] = sigf(zn);
    __syncthreads();

    if(t<32){
        float s = spwq_b[t];
        for(int c=0;c<64;c++) s += spwq_w[t*64+c]*pmean[c];
        float m=s;
        for(int off=16;off;off>>=1) m=fmaxf(m,__shfl_xor_sync(0xffffffffu,m,off));
        float e=expf(s-m), sum=e;
        for(int off=16;off;off>>=1) sum+=__shfl_xor_sync(0xffffffffu,sum,off);
        swq[t]=e/sum;
    }
    __syncthreads();

    float v=0.f;
    for(int j=0;j<32;j++) v += swq[j]*spwv_w[j*64+t];
    g_veff[p*64+t]=v;
    if(t==0){
        float b=0.f;
        for(int j=0;j<32;j++) b += swq[j]*spwv_b[j];
        g_beff[p]=b;
    }
}

// ================ K5: s-field (fp16 smem, q-tile 128) ================
__global__ void __launch_bounds__(256) k_sfield(const __half* __restrict__ ub, int khkw,
                                                size_t imgstride, int piBase,
                                                float* __restrict__ sf){
    __shared__ __half Vs[64*130];
    __shared__ float part[4*128];
    __shared__ float ve[64];
    int q0 = blockIdx.x*128, bp = blockIdx.y, n = blockIdx.z;
    int t = threadIdx.x;
    int pi = piBase + n*gridDim.y + bp;
    const __half* base = ub + (size_t)n*imgstride + (size_t)bp*64*khkw + q0;
    int qlim = khkw - q0; if(qlim>128) qlim=128;

    if(t<64) ve[t]=g_veff[pi*64+t];
    for(int i=t;i<4096;i+=256){
        int c=i>>6, j2=i&63;
        unsigned v = 0;
        if(j2*2 < qlim) v = *(const unsigned*)&base[(size_t)c*khkw + j2*2];
        *(unsigned*)&Vs[c*130 + j2*2] = v;
    }
    __syncthreads();
    {
        int j2=t&63, cg=t>>6;
        float sx=0.f, sy=0.f;
        #pragma unroll 8
        for(int cc=cg*16; cc<cg*16+16; cc++){
            float2 f = __half22float2(*(const __half2*)&Vs[cc*130 + j2*2]);
            float w = ve[cc];
            sx += w*f.x; sy += w*f.y;
        }
        part[cg*128 + j2*2]   = sx;
        part[cg*128 + j2*2+1] = sy;
    }
    __syncthreads();
    if(t<128 && t<qlim){
        float sd = part[t]+part[128+t]+part[256+t]+part[384+t] + g_beff[pi];
        sf[(size_t)n*(gridDim.y*khkw) + (size_t)bp*khkw + q0 + t] = sigf(sd);
    }
}

// ================ K6: s1 + div-free multiplier + retiled GEMM (4ob x 2px) ================
__global__ void __launch_bounds__(256) k6(const float* __restrict__ x, float* __restrict__ out){
    __shared__ __align__(16) float vs[256*PAD];   // rows 0..191 ex', rows 192..255 x
    __shared__ float s1s[32], icntS[32];
    __shared__ int q5s[32], cp05s[32];
    __shared__ int q3s[4][32], cp03s[4][32];
    __shared__ int nsegS[32];

    int t = threadIdx.x;
    int wt = blockIdx.x, h = blockIdx.y, n = blockIdx.z;
    int w0 = wt*32;

    const __half* exg = g_ex + (size_t)n*NO*HW + (size_t)h*Wd + w0;
    for(int i=t;i<768;i+=256){
        int k=i>>2, q=(i&3)*8;
        uint4 raw = *(const uint4*)&exg[(size_t)k*HW + q];
        __half2* hp = (__half2*)&raw;
        float2 f0=__half22float2(hp[0]), f1=__half22float2(hp[1]);
        float2 f2=__half22float2(hp[2]), f3=__half22float2(hp[3]);
        float* d = &vs[k*PAD+q];
        d[0]=f0.x; d[1]=f0.y; d[2]=f1.x; d[3]=f1.y;
        d[4]=f2.x; d[5]=f2.y; d[6]=f3.x; d[7]=f3.y;
    }
    const float* xp = x + (size_t)n*64*HW + (size_t)h*Wd + w0;
    for(int i=t;i<512;i+=256){
        int c=i>>3, grp=(i&7)*4;
        *(float4*)&vs[(192+c)*PAD+grp] = *(const float4*)&xp[(size_t)c*HW+grp];
    }
    if(t<32){
        int w = w0 + t;
        int rp5 = ((h&31)*32 + (w&31))*P5 + (h>>5)*5 + (w>>5);
        q5s[t] = rp5 & 1023; cp05s[t] = rp5 >> 10;
        int R[2], C[2];
        int nr = cover3(h, R), nc = cover3(w, C);
        nsegS[t] = nr*nc;
        icntS[t] = 1.f/(float)(nr*nc);
        for(int ri=0;ri<nr;ri++)
            for(int cj=0;cj<nc;cj++){
                int ph=R[ri], pw=C[cj];
                int rp3 = ((h-53*ph)*54 + (w-53*pw))*P3 + ph*3 + pw;
                int s = ri*nc + cj;
                cp03s[s][t] = rp3 / KHKW3;
                q3s[s][t]   = rp3 % KHKW3;
            }
    }
    __syncthreads();

    // win1 s-field from raw chunk0 (rows 0..63)
    if(t<32){
        float sd = g_beff[n];
        const float* ve = &g_veff[n*64];
        #pragma unroll
        for(int c=0;c<64;c++) sd += ve[c]*vs[c*PAD+t];
        s1s[t] = sigf(sd);
    }
    __syncthreads();

    // multiplier (div-free) on ex rows 0..191
    for(int i=t;i<NO*32;i+=256){
        int k=i>>5, pix=i&31, win=k>>6, ci=k&63;
        float m;
        if(win==0){
            m = g_gt[n*64+ci] + s1s[pix];
        } else if(win==2){
            int cpv = cp05s[pix] + 25*ci;
            int bp = cpv>>6, cp = cpv&63;
            m = g_gt[(160+n*25+bp)*64+cp] + g_sf5[n*25600 + (bp<<10) + q5s[pix]];
        } else {
            m = 0.f;
            int ns = nsegS[pix];
            #pragma unroll
            for(int s=0;s<4;s++){
                if(s>=ns) break;
                int cpv = cp03s[s][pix] + 9*ci;
                int bp = cpv>>6, cp = cpv&63;
                m += g_gt[(16+n*9+bp)*64+cp] + g_sf3[n*A3 + bp*KHKW3 + q3s[s][pix]];
            }
            m *= icntS[pix];
        }
        vs[k*PAD+pix] *= (1.f + m);
    }
    __syncthreads();

    // GEMM: out[64ob][32px] = Wall[256k][64ob]^T @ vs[256k][32px]
    // thread tile: 4 ob x 2 px ; per k: 1 LDS.64 + 1 LDG.128 + 4 FFMA2
    int pxp = t&15, px = pxp*2;
    int obg = t>>4, ob0 = obg*4;

    u64 acc0 = pk2(g_vb[ob0  ], g_vb[ob0  ]);
    u64 acc1 = pk2(g_vb[ob0+1], g_vb[ob0+1]);
    u64 acc2 = pk2(g_vb[ob0+2], g_vb[ob0+2]);
    u64 acc3 = pk2(g_vb[ob0+3], g_vb[ob0+3]);

    #pragma unroll 4
    for(int k=0;k<256;k++){
        u64 dv = *(const u64*)&vs[k*PAD+px];
        float4 wv = __ldg((const float4*)&g_Wall[k*64 + ob0]);
        fma2(acc0, pk2(wv.x,wv.x), dv);
        fma2(acc1, pk2(wv.y,wv.y), dv);
        fma2(acc2, pk2(wv.z,wv.z), dv);
        fma2(acc3, pk2(wv.w,wv.w), dv);
    }

    float* og = out + (size_t)n*64*HW + (size_t)h*Wd + w0 + px;
    float2 r0=up2(acc0), r1=up2(acc1), r2=up2(acc2), r3=up2(acc3);
    *(float2*)&og[(size_t)(ob0  )*HW] = r0;
    *(float2*)&og[(size_t)(ob0+1)*HW] = r1;
    *(float2*)&og[(size_t)(ob0+2)*HW] = r2;
    *(float2*)&og[(size_t)(ob0+3)*HW] = r3;
}

// ================ launch ================
extern "C" void kernel_launch(void* const* d_in, const int* in_sizes, int n_in,
                              void* d_out, int out_size){
    const float* x      = (const float*)d_in[0];
    const float* exp_w  = (const float*)d_in[1];
    const float* exp_b  = (const float*)d_in[2];
    const float* res_w  = (const float*)d_in[3];
    const float* res_b  = (const float*)d_in[4];
    const float* fus_w  = (const float*)d_in[5];
    const float* fus_b  = (const float*)d_in[6];
    const float* chwv_w = (const float*)d_in[7];
    const float* chwv_b = (const float*)d_in[8];
    const float* chwq_w = (const float*)d_in[9];
    const float* chwq_b = (const float*)d_in[10];
    const float* chwz_w = (const float*)d_in[11];
    const float* chwz_b = (const float*)d_in[12];
    const float* ln_g   = (const float*)d_in[13];
    const float* ln_b   = (const float*)d_in[14];
    const float* spwv_w = (const float*)d_in[15];
    const float* spwv_b = (const float*)d_in[16];
    const float* spwq_w = (const float*)d_in[17];
    const float* spwq_b = (const float*)d_in[18];
    float* out = (float*)d_out;

    __half *g_u3_p, *g_u5_p;
    float *g_sf3_p, *g_sf5_p;
    cudaGetSymbolAddress((void**)&g_u3_p, g_u3);
    cudaGetSymbolAddress((void**)&g_u5_p, g_u5);
    cudaGetSymbolAddress((void**)&g_sf3_p, g_sf3);
    cudaGetSymbolAddress((void**)&g_sf5_p, g_sf5);

    k_zero<<<(NPI*64+255)/256, 256>>>();
    k_wprep<<<1, 256>>>(exp_w, res_w, res_b, fus_w, fus_b);

    dim3 grid(Wd/32, Hh, NIMG);
    k1<<<grid, 256>>>(x, exp_b, chwq_w, chwq_b);

    k2_5<<<dim3(32,NIMG), 256>>>();
    k2_3<<<dim3(54,NIMG), 256>>>();

    k_stats<<<dim3(23,  9, NIMG), 256>>>(g_u3_p, KHKW3,(size_t)U3IMG, 16,  chwq_w, chwq_b);
    k_stats<<<dim3(8,  25, NIMG), 256>>>(g_u5_p, KHKW5,(size_t)U5IMG, 160, chwq_w, chwq_b);

    k4<<<NPI, 64>>>(chwv_w, chwv_b, chwz_w, chwz_b, ln_g, ln_b,
                    spwq_w, spwq_b, spwv_w, spwv_b);

    k_sfield<<<dim3(23,  9, NIMG), 256>>>(g_u3_p, KHKW3,(size_t)U3IMG, 16,  g_sf3_p);
    k_sfield<<<dim3(8,  25, NIMG), 256>>>(g_u5_p, KHKW5,(size_t)U5IMG, 160, g_sf5_p);

    k6<<<grid, 256>>>(x, out);
}